// round 13
// baseline (speedup 1.0000x reference)
#include <cuda_runtime.h>
#include <math.h>

#define THREADS    128
#define QPT        4                 // queries per thread
#define QPB        (THREADS * QPT)   // 512 queries per block
#define TILE_PAIRS 576               // smem: 576 * 32B = 18,432 B (incl. prefetch pad)
#define MAX_PPS    572               // pps <= 572; ceil(572/4)=143 <= 255 byte bound

typedef unsigned long long u64;
typedef unsigned int u32;

__device__ __forceinline__ u64 pk2(float a, float b) {
    u64 r; asm("mov.b64 %0, {%1, %2};" : "=l"(r) : "f"(a), "f"(b)); return r;
}

// One m-pair vs one query, 3 FFMA2 only:
//   r' = bx*X + by*Y + bz*Z + C4,  C4 = a2 - 0.25 + 8  (per-m, staged)
//   count iff r' < T' where T' = 8 - b2 (per query).
// r' and T' are strictly positive floats, so float< == int< on bit patterns.
// The compare runs on the ALU pipe: per-lane sub.s32, then PRMT msb-replicate
// places the two sign bytes at {0,1} (ctl 0x00FB) or {2,3} (ctl 0xFB00).
__device__ __forceinline__ u32 pair_cmp(u64 X, u64 Y, u64 Z, u64 C4,
                                        u64 bx2, u64 by2, u64 bz2, u32 Tint,
                                        u32 ctl) {
    u32 q;
    asm("{\n\t"
        ".reg .b64 t;\n\t"
        ".reg .b32 lo, hi, d0, d1;\n\t"
        "fma.rn.f32x2 t, %1, %2, %3;\n\t"     // t  = bx*X + C4
        "fma.rn.f32x2 t, %4, %5, t;\n\t"      // t += by*Y
        "fma.rn.f32x2 t, %6, %7, t;\n\t"      // t += bz*Z
        "mov.b64 {lo, hi}, t;\n\t"
        "sub.s32 d0, lo, %8;\n\t"             // int(r'_lane) - int(T') < 0 => count
        "sub.s32 d1, hi, %8;\n\t"
        "prmt.b32 %0, d0, d1, %9;\n\t"
        "}"
        : "=r"(q)
        : "l"(bx2), "l"(X), "l"(C4),
          "l"(by2), "l"(Y),
          "l"(bz2), "l"(Z),
          "r"(Tint), "r"(ctl));
    return q;
}

__global__ void __launch_bounds__(THREADS, 6) count_kernel(
    const float* __restrict__ pc,   // queries [N,3]
    const float* __restrict__ pad,  // padding [M,3]
    int N, int M, int pairs, int pps, float* __restrict__ out)
{
    __shared__ ulonglong2 sh[2 * TILE_PAIRS];   // per pair: {X01,Y01},{Z01,C01}
    const float INF = __int_as_float(0x7f800000);

    int p0 = blockIdx.y * pps;
    int np = pairs - p0;
    if (np > pps) np = pps;
    int np4 = (np + 3) & ~3;        // multiple of 4 pairs (two 2-pair stages)
    int npad = np4 + 2;             // +2 sentinel pairs for branch-free prefetch

    // Stage + pack this m-slice: X=-2x, Y=-2y, Z=-2z, C4 = a2 - 0.25 + 8.
    for (int i = threadIdx.x; i < np; i += THREADS) {
        int p  = p0 + i;
        int m0 = 2 * p, m1 = 2 * p + 1;
        float x0 = pad[3 * m0], y0 = pad[3 * m0 + 1], z0 = pad[3 * m0 + 2];
        float c0 = fmaf(x0, x0, fmaf(y0, y0, z0 * z0)) + 7.75f;
        float x1 = 0.f, y1 = 0.f, z1 = 0.f, c1 = INF;   // sentinel never counts
        if (m1 < M) {
            x1 = pad[3 * m1]; y1 = pad[3 * m1 + 1]; z1 = pad[3 * m1 + 2];
            c1 = fmaf(x1, x1, fmaf(y1, y1, z1 * z1)) + 7.75f;
        }
        sh[2 * i]     = make_ulonglong2(pk2(-2.f * x0, -2.f * x1),
                                        pk2(-2.f * y0, -2.f * y1));
        sh[2 * i + 1] = make_ulonglong2(pk2(-2.f * z0, -2.f * z1),
                                        pk2(c0, c1));
    }
    for (int i = np + threadIdx.x; i < npad; i += THREADS) {
        sh[2 * i]     = make_ulonglong2(0ull, 0ull);
        sh[2 * i + 1] = make_ulonglong2(0ull, pk2(INF, INF));
    }
    __syncthreads();

    // 4 queries per thread: n0 + k*THREADS.
    int n0 = blockIdx.x * QPB + threadIdx.x;
    u64 bx2[QPT], by2[QPT], bz2[QPT];
    u32 Tint[QPT];
#pragma unroll
    for (int k = 0; k < QPT; ++k) {
        int n = n0 + k * THREADS;
        float bx = 0.f, by = 0.f, bz = 0.f;
        u32 ti = 0u;                         // int(+0.0): r' > 0 => never counts
        if (n < N) {
            bx = pc[3 * n]; by = pc[3 * n + 1]; bz = pc[3 * n + 2];
            float b2 = fmaf(bx, bx, fmaf(by, by, bz * bz));
            ti = __float_as_uint(8.0f - b2); // T' in (5,8], positive
        }
        bx2[k] = pk2(bx, bx); by2[k] = pk2(by, by); bz2[k] = pk2(bz, bz);
        Tint[k] = ti;
    }

    // Software-pipelined mainloop (R12 structure): stage = 2 pairs in regs;
    // prefetch next stage's 4 LDS.128 before computing. Two stages per loop
    // iteration alternate acc banks: each byte +1 per 2 stages (<=143).
    u32 acc[8] = {0, 0, 0, 0, 0, 0, 0, 0};

    ulonglong2 cA0 = sh[0], cB0 = sh[1], cA1 = sh[2], cB1 = sh[3];

#define STAGE(BANK)                                                            \
    do {                                                                       \
        u32 q0 = pair_cmp(cA0.x, cA0.y, cB0.x, cB0.y,                          \
                          bx2[0], by2[0], bz2[0], Tint[0], 0x00FBu);           \
        u32 q1 = pair_cmp(cA0.x, cA0.y, cB0.x, cB0.y,                          \
                          bx2[1], by2[1], bz2[1], Tint[1], 0xFB00u);           \
        acc[(BANK) + 0] += (q0 & 0x00000101u) + (q1 & 0x01010000u);            \
        u32 q2 = pair_cmp(cA0.x, cA0.y, cB0.x, cB0.y,                          \
                          bx2[2], by2[2], bz2[2], Tint[2], 0x00FBu);           \
        u32 q3 = pair_cmp(cA0.x, cA0.y, cB0.x, cB0.y,                          \
                          bx2[3], by2[3], bz2[3], Tint[3], 0xFB00u);           \
        acc[(BANK) + 1] += (q2 & 0x00000101u) + (q3 & 0x01010000u);            \
        u32 r0 = pair_cmp(cA1.x, cA1.y, cB1.x, cB1.y,                          \
                          bx2[0], by2[0], bz2[0], Tint[0], 0x00FBu);           \
        u32 r1 = pair_cmp(cA1.x, cA1.y, cB1.x, cB1.y,                          \
                          bx2[1], by2[1], bz2[1], Tint[1], 0xFB00u);           \
        acc[(BANK) + 2] += (r0 & 0x00000101u) + (r1 & 0x01010000u);            \
        u32 r2 = pair_cmp(cA1.x, cA1.y, cB1.x, cB1.y,                          \
                          bx2[2], by2[2], bz2[2], Tint[2], 0x00FBu);           \
        u32 r3 = pair_cmp(cA1.x, cA1.y, cB1.x, cB1.y,                          \
                          bx2[3], by2[3], bz2[3], Tint[3], 0xFB00u);           \
        acc[(BANK) + 3] += (r2 & 0x00000101u) + (r3 & 0x01010000u);            \
    } while (0)

    for (int j = 0; j < np4; j += 4) {
        // ---- stage A: pairs j, j+1 (prefetch j+2, j+3 first) ----
        const ulonglong2* Pn = sh + 2 * (j + 2);
        ulonglong2 nA0 = Pn[0], nB0 = Pn[1], nA1 = Pn[2], nB1 = Pn[3];
        STAGE(0);
        cA0 = nA0; cB0 = nB0; cA1 = nA1; cB1 = nB1;

        // ---- stage B: pairs j+2, j+3 (prefetch j+4, j+5 first) ----
        const ulonglong2* Pm = sh + 2 * (j + 4);
        ulonglong2 mA0 = Pm[0], mB0 = Pm[1], mA1 = Pm[2], mB1 = Pm[3];
        STAGE(4);
        cA0 = mA0; cB0 = mB0; cA1 = mA1; cB1 = mB1;
    }
#undef STAGE

    // Unsigned per-byte reduction, separated per query (bytes <= 143).
    u32 c[QPT] = {0, 0, 0, 0};
#pragma unroll
    for (int s = 0; s < 2; ++s) {           // slot (m-pair position in stage)
#pragma unroll
        for (int bank = 0; bank < 8; bank += 4) {
            u32 a = acc[bank + 2 * s], b = acc[bank + 2 * s + 1];
            c[0] += (a & 0xFFu) + ((a >> 8) & 0xFFu);
            c[1] += ((a >> 16) & 0xFFu) + (a >> 24);
            c[2] += (b & 0xFFu) + ((b >> 8) & 0xFFu);
            c[3] += ((b >> 16) & 0xFFu) + (b >> 24);
        }
    }
#pragma unroll
    for (int k = 0; k < QPT; ++k) {
        int n = n0 + k * THREADS;
        if (n < N) atomicAdd(out + n, (float)c[k]);
    }
}

extern "C" void kernel_launch(void* const* d_in, const int* in_sizes, int n_in,
                              void* d_out, int out_size) {
    // The input with 3*out_size elements IS the pointcloud (output rows = N).
    int N = out_size;
    const float* pc;
    const float* pad;
    int M;
    if (in_sizes[0] == 3 * out_size) {
        pc  = (const float*)d_in[0];
        pad = (const float*)d_in[1];
        M   = in_sizes[1] / 3;
    } else {
        pc  = (const float*)d_in[1];
        pad = (const float*)d_in[0];
        M   = in_sizes[0] / 3;
    }

    int pairs  = (M + 1) / 2;                        // 12500
    int msplit = (pairs + MAX_PPS - 1) / MAX_PPS;    // 22
    if (msplit < 1) msplit = 1;
    int pps    = (pairs + msplit - 1) / msplit;      // 569 (<= 572)

    int nx = (N + QPB - 1) / QPB;                    // 40
    float* out = (float*)d_out;
    // Zero output (atomic accumulation target); memset node is graph-capturable.
    cudaMemsetAsync(out, 0, (size_t)out_size * sizeof(float), 0);
    dim3 grid(nx, msplit);                           // 40 x 22 = 880 blocks
    count_kernel<<<grid, THREADS>>>(pc, pad, N, M, pairs, pps, out);
}

// round 14
// speedup vs baseline: 1.0242x; 1.0242x over previous
#include <cuda_runtime.h>
#include <math.h>

#define THREADS    128
#define QPT        4                 // queries per thread
#define QPB        (THREADS * QPT)   // 512 queries per block
#define TILE_PAIRS 576               // smem: 576 * 32B = 18,432 B
#define MAX_PPS    572               // pps <= 572; ceil(572/4)=143 <= 255 byte bound

typedef unsigned long long u64;
typedef unsigned int u32;

__device__ __forceinline__ u64 pk2(float a, float b) {
    u64 r; asm("mov.b64 %0, {%1, %2};" : "=l"(r) : "f"(a), "f"(b)); return r;
}
// Single-instruction helpers (non-volatile): ptxas is free to interleave
// chains from different pairs/queries and exploit operand-reuse.
__device__ __forceinline__ u64 fma2(u64 a, u64 b, u64 c) {
    u64 d; asm("fma.rn.f32x2 %0, %1, %2, %3;" : "=l"(d) : "l"(a), "l"(b), "l"(c)); return d;
}
__device__ __forceinline__ u64 add2(u64 a, u64 b) {
    u64 d; asm("add.rn.f32x2 %0, %1, %2;" : "=l"(d) : "l"(a), "l"(b)); return d;
}
// Sign bytes of the two f32 lanes of t via PRMT msb-replicate; the mov.b64
// split is a register rename (no SASS op). ctl 0x00FB -> bytes {0,1};
// ctl 0xFB00 -> bytes {2,3}.
__device__ __forceinline__ u32 sgn2(u64 t, u32 ctl) {
    u32 q;
    asm("{\n\t.reg .b32 lo, hi;\n\tmov.b64 {lo, hi}, %1;\n\t"
        "prmt.b32 %0, lo, hi, %2;\n\t}"
        : "=r"(q) : "l"(t), "r"(ctl));
    return q;
}

// s = b2 + (a2-0.25) - 2(x*bx+y*by+z*bz) = d2 - 0.25; count iff s < 0.
// Matches reference's sqrt(max(d2,0)) <= 0.5 up to reassociation ties (8.1e-6).
__global__ void __launch_bounds__(THREADS, 6) count_kernel(
    const float* __restrict__ pc,   // queries [N,3]
    const float* __restrict__ pad,  // padding [M,3]
    int N, int M, int pairs, int pps, float* __restrict__ out)
{
    __shared__ ulonglong2 sh[2 * TILE_PAIRS];   // per pair: {X01,Y01},{Z01,C01}
    const float INF = __int_as_float(0x7f800000);

    int p0 = blockIdx.y * pps;
    int np = pairs - p0;
    if (np > pps) np = pps;
    int np4 = (np + 3) & ~3;        // multiple of 4 pairs

    // Stage + pack this m-slice: X=-2x, Y=-2y, Z=-2z, C = a2 - 0.25.
    for (int i = threadIdx.x; i < np; i += THREADS) {
        int p  = p0 + i;
        int m0 = 2 * p, m1 = 2 * p + 1;
        float x0 = pad[3 * m0], y0 = pad[3 * m0 + 1], z0 = pad[3 * m0 + 2];
        float c0 = fmaf(x0, x0, fmaf(y0, y0, z0 * z0)) - 0.25f;
        float x1 = 0.f, y1 = 0.f, z1 = 0.f, c1 = INF;   // sentinel never counts
        if (m1 < M) {
            x1 = pad[3 * m1]; y1 = pad[3 * m1 + 1]; z1 = pad[3 * m1 + 2];
            c1 = fmaf(x1, x1, fmaf(y1, y1, z1 * z1)) - 0.25f;
        }
        sh[2 * i]     = make_ulonglong2(pk2(-2.f * x0, -2.f * x1),
                                        pk2(-2.f * y0, -2.f * y1));
        sh[2 * i + 1] = make_ulonglong2(pk2(-2.f * z0, -2.f * z1),
                                        pk2(c0, c1));
    }
    for (int i = np + threadIdx.x; i < np4; i += THREADS) {
        sh[2 * i]     = make_ulonglong2(0ull, 0ull);
        sh[2 * i + 1] = make_ulonglong2(0ull, pk2(INF, INF));
    }
    __syncthreads();

    // 4 queries per thread: n0 + k*THREADS.
    int n0 = blockIdx.x * QPB + threadIdx.x;
    u64 bx2[QPT], by2[QPT], bz2[QPT], b2p[QPT];
#pragma unroll
    for (int k = 0; k < QPT; ++k) {
        int n = n0 + k * THREADS;
        float bx = 0.f, by = 0.f, bz = 0.f, b2 = INF;
        if (n < N) {
            bx = pc[3 * n]; by = pc[3 * n + 1]; bz = pc[3 * n + 2];
            b2 = fmaf(bx, bx, fmaf(by, by, bz * bz));
        }
        bx2[k] = pk2(bx, bx); by2[k] = pk2(by, by);
        bz2[k] = pk2(bz, bz); b2p[k] = pk2(b2, b2);
    }

    // Mainloop: 4 pairs per iteration as two 2-pair groups with alternating
    // acc banks (each byte +1 per iteration, <=143). All 8 chains per group
    // are independent — ptxas interleaves them to hide fma latency.
    u32 acc[8] = {0, 0, 0, 0, 0, 0, 0, 0};

#define GROUP(A0, B0, A1, B1, BANK)                                           \
    do {                                                                      \
        u64 t0, t1, t2, t3, u0, u1, u2, u3;                                   \
        t0 = fma2(bx2[0], (A0).x, (B0).y);                                    \
        t1 = fma2(bx2[1], (A0).x, (B0).y);                                    \
        t2 = fma2(bx2[2], (A0).x, (B0).y);                                    \
        t3 = fma2(bx2[3], (A0).x, (B0).y);                                    \
        u0 = fma2(bx2[0], (A1).x, (B1).y);                                    \
        u1 = fma2(bx2[1], (A1).x, (B1).y);                                    \
        u2 = fma2(bx2[2], (A1).x, (B1).y);                                    \
        u3 = fma2(bx2[3], (A1).x, (B1).y);                                    \
        t0 = fma2(by2[0], (A0).y, t0);  t1 = fma2(by2[1], (A0).y, t1);        \
        t2 = fma2(by2[2], (A0).y, t2);  t3 = fma2(by2[3], (A0).y, t3);        \
        u0 = fma2(by2[0], (A1).y, u0);  u1 = fma2(by2[1], (A1).y, u1);        \
        u2 = fma2(by2[2], (A1).y, u2);  u3 = fma2(by2[3], (A1).y, u3);        \
        t0 = fma2(bz2[0], (B0).x, t0);  t1 = fma2(bz2[1], (B0).x, t1);        \
        t2 = fma2(bz2[2], (B0).x, t2);  t3 = fma2(bz2[3], (B0).x, t3);        \
        u0 = fma2(bz2[0], (B1).x, u0);  u1 = fma2(bz2[1], (B1).x, u1);        \
        u2 = fma2(bz2[2], (B1).x, u2);  u3 = fma2(bz2[3], (B1).x, u3);        \
        t0 = add2(t0, b2p[0]);  t1 = add2(t1, b2p[1]);                        \
        t2 = add2(t2, b2p[2]);  t3 = add2(t3, b2p[3]);                        \
        u0 = add2(u0, b2p[0]);  u1 = add2(u1, b2p[1]);                        \
        u2 = add2(u2, b2p[2]);  u3 = add2(u3, b2p[3]);                        \
        u32 s0 = sgn2(t0, 0x00FBu), s1 = sgn2(t1, 0xFB00u);                   \
        u32 s2 = sgn2(t2, 0x00FBu), s3 = sgn2(t3, 0xFB00u);                   \
        u32 v0 = sgn2(u0, 0x00FBu), v1 = sgn2(u1, 0xFB00u);                   \
        u32 v2 = sgn2(u2, 0x00FBu), v3 = sgn2(u3, 0xFB00u);                   \
        acc[(BANK) + 0] += (s0 & 0x00000101u) + (s1 & 0x01010000u);           \
        acc[(BANK) + 1] += (s2 & 0x00000101u) + (s3 & 0x01010000u);           \
        acc[(BANK) + 2] += (v0 & 0x00000101u) + (v1 & 0x01010000u);           \
        acc[(BANK) + 3] += (v2 & 0x00000101u) + (v3 & 0x01010000u);           \
    } while (0)

#pragma unroll 1
    for (int j = 0; j < np4; j += 4) {
        const ulonglong2* P = sh + 2 * j;
        ulonglong2 A0 = P[0], B0 = P[1], A1 = P[2], B1 = P[3];
        ulonglong2 A2 = P[4], B2 = P[5], A3 = P[6], B3 = P[7];
        GROUP(A0, B0, A1, B1, 0);
        GROUP(A2, B2, A3, B3, 4);
    }
#undef GROUP

    // Unsigned per-byte reduction, separated per query (bytes <= 143).
    // acc[g+0]: q0,q1 of even pair; acc[g+1]: q2,q3 even; acc[g+2]: q0,q1 odd;
    // acc[g+3]: q2,q3 odd — for g in {0,4}.
    u32 c[QPT] = {0, 0, 0, 0};
#pragma unroll
    for (int g = 0; g < 8; g += 4) {
#pragma unroll
        for (int s = 0; s < 2; ++s) {
            u32 a = acc[g + 2 * s];       // q0,q1
            u32 b = acc[g + 2 * s + 1];   // q2,q3
            c[0] += (a & 0xFFu) + ((a >> 8) & 0xFFu);
            c[1] += ((a >> 16) & 0xFFu) + (a >> 24);
            c[2] += (b & 0xFFu) + ((b >> 8) & 0xFFu);
            c[3] += ((b >> 16) & 0xFFu) + (b >> 24);
        }
    }
#pragma unroll
    for (int k = 0; k < QPT; ++k) {
        int n = n0 + k * THREADS;
        if (n < N) atomicAdd(out + n, (float)c[k]);
    }
}

extern "C" void kernel_launch(void* const* d_in, const int* in_sizes, int n_in,
                              void* d_out, int out_size) {
    // The input with 3*out_size elements IS the pointcloud (output rows = N).
    int N = out_size;
    const float* pc;
    const float* pad;
    int M;
    if (in_sizes[0] == 3 * out_size) {
        pc  = (const float*)d_in[0];
        pad = (const float*)d_in[1];
        M   = in_sizes[1] / 3;
    } else {
        pc  = (const float*)d_in[1];
        pad = (const float*)d_in[0];
        M   = in_sizes[0] / 3;
    }

    int pairs  = (M + 1) / 2;                        // 12500
    int msplit = (pairs + MAX_PPS - 1) / MAX_PPS;    // 22
    if (msplit < 1) msplit = 1;
    int pps    = (pairs + msplit - 1) / msplit;      // 569 (<= 572)

    int nx = (N + QPB - 1) / QPB;                    // 40
    float* out = (float*)d_out;
    // Zero output (atomic accumulation target); memset node is graph-capturable.
    cudaMemsetAsync(out, 0, (size_t)out_size * sizeof(float), 0);
    dim3 grid(nx, msplit);                           // 40 x 22 = 880 blocks
    count_kernel<<<grid, THREADS>>>(pc, pad, N, M, pairs, pps, out);
}